// round 14
// baseline (speedup 1.0000x reference)
#include <cuda_runtime.h>
#include <cuda_fp16.h>
#include <math.h>
#include <cstdint>

#define HW     16384
#define IMG_H  128
#define IMG_W  128
#define BSZ    4
#define CIN    720
#define MID    512
#define NCLS   19
#define KCH    256
#define VCH    256

#define PH 130
#define PW 130

// conv tiling: CTA 128(m) x 128(n), K-chunk 48, 4 warps (2m x 2n), warp tile 64x64, 2 CTAs/SM
#define KCH_C     48
#define NCHUNKS   135
#define ASTRIDE   56
#define REG_A_ELE (128*ASTRIDE)          // 7168 halfs
#define STG_ELE   (2*REG_A_ELE)          // A + B
#define STG_BYTES (STG_ELE*2)            // 28672
#define SMEM_DYN  67584                  // max(2*STG_BYTES=57344, epilogue 128*132*4)

// gemm2 tiling (R11/R12 proven)
#define G2_STR    40
#define G2_REG    (128*G2_STR)
#define G2_STAGE  (3*G2_REG*2)           // 30720
#define G2_SMEM   67584

// ---------------- scratch ----------------
__device__ float g_x    [BSZ*MID*HW];
__device__ float g_q    [BSZ*HW*KCH];
__device__ float g_probs[BSZ*NCLS*HW];
__device__ float g_S    [BSZ*NCLS];
__device__ float g_ctx  [BSZ*NCLS*MID];
__device__ float g_kmat [BSZ*NCLS*KCH];
__device__ float g_vmat [BSZ*NCLS*VCH];
__device__ float g_scale[MID];
__device__ float g_shift[MID];
__device__ __align__(16) __half g_fhi[BSZ*PH*PW*CIN];
__device__ __align__(16) __half g_whi[9*MID*CIN];
__device__ __align__(16) __half g_xh16[BSZ*HW*MID];
__device__ __align__(16) __half g_xl16[BSZ*HW*MID];
__device__ __align__(16) __half g_aggh[BSZ*HW*VCH];
__device__ __align__(16) __half g_aggl[BSZ*HW*VCH];
__device__ __align__(16) __half g_qw16[KCH*MID];
__device__ __align__(16) __half g_ow16[MID*VCH];

// ---------------- helpers ----------------
__device__ __forceinline__ uint32_t smem_u32(const void* p) {
    uint32_t a;
    asm("{ .reg .u64 t; cvta.to.shared.u64 t, %1; cvt.u32.u64 %0, t; }" : "=r"(a) : "l"(p));
    return a;
}
__device__ __forceinline__ void cp16(uint32_t s, const void* g) {
    asm volatile("cp.async.cg.shared.global [%0], [%1], 16;" :: "r"(s), "l"(g));
}
__device__ __forceinline__ void cp_commit() {
    asm volatile("cp.async.commit_group;");
}
__device__ __forceinline__ void mma16816(float* d, const uint32_t* a, const uint32_t* b) {
    asm volatile(
        "mma.sync.aligned.m16n8k16.row.col.f32.f16.f16.f32 "
        "{%0,%1,%2,%3}, {%4,%5,%6,%7}, {%8,%9}, {%0,%1,%2,%3};"
        : "+f"(d[0]), "+f"(d[1]), "+f"(d[2]), "+f"(d[3])
        : "r"(a[0]), "r"(a[1]), "r"(a[2]), "r"(a[3]), "r"(b[0]), "r"(b[1]));
}

// ---------------- prep ----------------
__global__ void zero_pad() {
    long i = (long)blockIdx.x * 256 + threadIdx.x;
    const long n4 = (long)BSZ*PH*PW*CIN / 8;
    if (i < n4) ((float4*)g_fhi)[i] = make_float4(0.f, 0.f, 0.f, 0.f);
}

__global__ __launch_bounds__(256) void nhwc_prep(const float* __restrict__ feats) {
    __shared__ float tile[64][129];
    int by = blockIdx.x;
    int b = by >> 7, h = by & 127;
    int tid = threadIdx.x;
    const float* fb = feats + ((long)b * CIN) * HW + h * IMG_W;
    long obase = ((long)(b * PH + h + 1) * PW + 1) * CIN;
    for (int c0 = 0; c0 < CIN; c0 += 64) {
        int cw = CIN - c0; if (cw > 64) cw = 64;
        #pragma unroll 4
        for (int j = 0; j < 32; j++) {
            int idx = tid + j * 256;
            int c = idx >> 7, w = idx & 127;
            if (c < cw) tile[c][w] = fb[(long)(c0 + c) * HW + w];
        }
        __syncthreads();
        #pragma unroll 4
        for (int j = 0; j < 32; j++) {
            int idx = tid + j * 256;
            int w = idx >> 6, c = idx & 63;
            if (c < cw)
                g_fhi[obase + (long)w * CIN + c0 + c] = __float2half_rn(tile[c][w]);
        }
        __syncthreads();
    }
}

__global__ void w3_prep(const float* __restrict__ w3) {
    int e = blockIdx.x * 256 + threadIdx.x;
    if (e >= 9 * MID * CIN) return;
    int r = e / (MID * CIN);
    int rem = e - r * (MID * CIN);
    int o = rem / CIN;
    int c = rem - o * CIN;
    g_whi[e] = __float2half_rn(w3[(o * CIN + c) * 9 + r]);
}

__global__ void w16_prep(const float* __restrict__ qw, const float* __restrict__ ow) {
    int i = blockIdx.x * 256 + threadIdx.x;
    if (i < KCH*MID) g_qw16[i] = __float2half_rn(qw[i]);
    if (i < MID*VCH) g_ow16[i] = __float2half_rn(ow[i]);
}

__global__ void zero_kernel() {
    int i = blockIdx.x * 256 + threadIdx.x;
    if (i < BSZ*NCLS*MID) g_ctx[i] = 0.f;
    if (i < BSZ*NCLS)     g_S[i]   = 0.f;
}

// ---------------- conv3x3: CTA 128x128, 4 warps, warp tile 64x64, 2 CTAs/SM ----------------
__global__ void __launch_bounds__(128, 2) conv_mma() {
    extern __shared__ __half sm[];
    uint32_t sbase = smem_u32(sm);
    int tid = threadIdx.x;
    int lane = tid & 31, warp = tid >> 5;
    int wm = warp & 1, wn = warp >> 1;           // 2m x 2n
    int qrow = lane >> 2, qcol = (lane & 3) * 2;
    int bn = blockIdx.x * 128;
    int by = blockIdx.y;
    int b = by >> 7, h = by & 127;

    const __half* fhi_b = g_fhi + (long)b * PH * PW * CIN;

    // loader: each thread owns A row tid and B row tid (48 halfs each, 6x cp16)
    uint32_t thr_s = (uint32_t)(tid * ASTRIDE) * 2;

    float d[4][8][4];
    #pragma unroll
    for (int mt = 0; mt < 4; mt++)
        #pragma unroll
        for (int nt = 0; nt < 8; nt++)
            #pragma unroll
            for (int e = 0; e < 4; e++) d[mt][nt][e] = 0.f;

    int nr = 0, nci = 0, nc0 = 0;

    // prologue: chunk 0 -> stage 0
    {
        int ab = h * PW * CIN + tid * CIN;
        int bb = (bn + tid) * CIN;
        uint32_t st = sbase;
        #pragma unroll
        for (int j = 0; j < 6; j++) {
            cp16(st + thr_s + j*16,                 fhi_b + ab + j*8);
            cp16(st + REG_A_ELE*2 + thr_s + j*16,   g_whi + bb + j*8);
        }
        cp_commit();
    }
    nci = 1; nc0 = KCH_C;

    for (int it = 0; it < NCHUNKS; it++) {
        int s = it & 1;
        if (it + 1 < NCHUNKS) {
            int ky = nr / 3, kx = nr - ky * 3;
            int ab = ((h + ky) * PW + kx) * CIN + nc0 + tid * CIN;
            int bb = (nr * MID + bn + tid) * CIN + nc0;
            uint32_t st = sbase + (uint32_t)(1 - s) * STG_BYTES;
            #pragma unroll
            for (int j = 0; j < 6; j++) {
                cp16(st + thr_s + j*16,               fhi_b + ab + j*8);
                cp16(st + REG_A_ELE*2 + thr_s + j*16, g_whi + bb + j*8);
            }
            cp_commit();
            nci++; nc0 += KCH_C;
            if (nci == 15) { nci = 0; nc0 = 0; nr++; }
            asm volatile("cp.async.wait_group 1;");
        } else {
            asm volatile("cp.async.wait_group 0;");
        }
        __syncthreads();

        const __half* st = sm + (size_t)s * STG_ELE;
        const __half* Ah = st;
        const __half* Bh = st + REG_A_ELE;

        #pragma unroll
        for (int ks = 0; ks < 3; ks++) {
            int k0 = ks * 16 + qcol;
            uint32_t ah[4][4], bh[8][2];
            #pragma unroll
            for (int mt = 0; mt < 4; mt++) {
                int r0 = wm * 64 + mt * 16 + qrow;
                ah[mt][0] = *(const uint32_t*)(Ah + r0*ASTRIDE + k0);
                ah[mt][1] = *(const uint32_t*)(Ah + (r0+8)*ASTRIDE + k0);
                ah[mt][2] = *(const uint32_t*)(Ah + r0*ASTRIDE + k0 + 8);
                ah[mt][3] = *(const uint32_t*)(Ah + (r0+8)*ASTRIDE + k0 + 8);
            }
            #pragma unroll
            for (int nt = 0; nt < 8; nt++) {
                int n0r = wn * 64 + nt * 8 + qrow;
                bh[nt][0] = *(const uint32_t*)(Bh + n0r*ASTRIDE + k0);
                bh[nt][1] = *(const uint32_t*)(Bh + n0r*ASTRIDE + k0 + 8);
            }
            #pragma unroll
            for (int mt = 0; mt < 4; mt++)
                #pragma unroll
                for (int nt = 0; nt < 8; nt++)
                    mma16816(d[mt][nt], ah[mt], bh[nt]);
        }
        __syncthreads();
    }

    // epilogue: transpose through SMEM (128n x 132m), coalesced float4 stores
    float* es = (float*)sm;
    #pragma unroll
    for (int mt = 0; mt < 4; mt++) {
        int m = wm * 64 + mt * 16 + qrow;
        #pragma unroll
        for (int nt = 0; nt < 8; nt++) {
            int n = wn * 64 + nt * 8 + qcol;
            es[n*132 + m]       = d[mt][nt][0];
            es[(n+1)*132 + m]   = d[mt][nt][1];
            es[n*132 + m + 8]   = d[mt][nt][2];
            es[(n+1)*132 + m+8] = d[mt][nt][3];
        }
    }
    __syncthreads();
    {
        int n = tid;   // one full 128-float row per thread
        float* dst = g_x + ((long)(b * MID + bn + n)) * HW + h * IMG_W;
        const float* src = es + n*132;
        #pragma unroll
        for (int j = 0; j < 32; j++)
            ((float4*)dst)[j] = ((const float4*)src)[j];
    }
}

// ---------------- BN stats per channel ----------------
__global__ void bn_stats(const float* __restrict__ gamma, const float* __restrict__ beta) {
    int c = blockIdx.x, tid = threadIdx.x;
    float s = 0.f, sq = 0.f;
    for (int b = 0; b < BSZ; b++) {
        const float* p = g_x + (b*MID + c)*HW;
        for (int i = tid; i < HW; i += 256) { float v = p[i]; s += v; sq += v*v; }
    }
    __shared__ float ss[256], s2[256];
    ss[tid] = s; s2[tid] = sq; __syncthreads();
    for (int st = 128; st > 0; st >>= 1) {
        if (tid < st) { ss[tid] += ss[tid+st]; s2[tid] += s2[tid+st]; }
        __syncthreads();
    }
    if (tid == 0) {
        float n    = (float)(BSZ*HW);
        float mean = ss[0] / n;
        float var  = s2[0] / n - mean*mean;
        float rstd = rsqrtf(var + 1e-5f);
        float sc   = gamma[c] * rstd;
        g_scale[c] = sc;
        g_shift[c] = beta[c] - mean * sc;
    }
}

// ---------------- fused: BN apply + relu + fp16 split emit [pix][c] + aux + softmax ----------------
__global__ __launch_bounds__(256)
void bn_aux_softmax(const float* __restrict__ aux_w, const float* __restrict__ aux_b,
                    float* __restrict__ aux_out) {
    __shared__ float sw[NCLS*MID];
    __shared__ float ssc[MID], ssh[MID];
    __shared__ float sb[NCLS], sS[NCLS];
    int tid = threadIdx.x;
    for (int i = tid; i < NCLS*MID; i += 256) sw[i] = aux_w[i];
    for (int i = tid; i < MID; i += 256) { ssc[i] = g_scale[i]; ssh[i] = g_shift[i]; }
    if (tid < NCLS) { sb[tid] = aux_b[tid]; sS[tid] = 0.f; }
    __syncthreads();

    int pix = blockIdx.x * 256 + tid;
    int b   = pix >> 14;
    int hw  = pix & (HW-1);
    float acc[NCLS];
    #pragma unroll
    for (int k = 0; k < NCLS; k++) acc[k] = 0.f;

    float* xb = g_x + (long)b * MID * HW + hw;
    long pbase = (long)pix * MID;
    for (int c0 = 0; c0 < MID; c0 += 8) {
        __align__(16) __half hb[8];
        __align__(16) __half lb[8];
        #pragma unroll
        for (int cc = 0; cc < 8; cc++) {
            int c = c0 + cc;
            float v = xb[(long)c*HW];
            v = fmaf(v, ssc[c], ssh[c]);
            v = fmaxf(v, 0.f);
            xb[(long)c*HW] = v;
            __half hv = __float2half_rn(v);
            hb[cc] = hv;
            lb[cc] = __float2half_rn(v - __half2float(hv));
            #pragma unroll
            for (int k = 0; k < NCLS; k++) acc[k] = fmaf(v, sw[k*MID + c], acc[k]);
        }
        *(uint4*)&g_xh16[pbase + c0] = *(const uint4*)hb;
        *(uint4*)&g_xl16[pbase + c0] = *(const uint4*)lb;
    }
    float mx = -1e30f;
    #pragma unroll
    for (int k = 0; k < NCLS; k++) {
        acc[k] += sb[k];
        aux_out[(b*NCLS + k)*HW + hw] = acc[k];
        mx = fmaxf(mx, acc[k]);
    }
    float sum = 0.f;
    #pragma unroll
    for (int k = 0; k < NCLS; k++) { acc[k] = expf(acc[k] - mx); sum += acc[k]; }
    float inv = 1.f / sum;
    #pragma unroll
    for (int k = 0; k < NCLS; k++) {
        float p = acc[k] * inv;
        g_probs[(b*NCLS + k)*HW + hw] = p;
        atomicAdd(&sS[k], p);
    }
    __syncthreads();
    if (tid < NCLS) atomicAdd(&g_S[b*NCLS + tid], sS[tid]);
}

// ---------------- context ----------------
__global__ __launch_bounds__(512)
void context_kernel() {
    __shared__ float pw[NCLS][512];
    int b   = blockIdx.y;
    int n0  = blockIdx.x * 512;
    int tid = threadIdx.x;
    for (int k = 0; k < NCLS; k++)
        pw[k][tid] = g_probs[(b*NCLS + k)*HW + n0 + tid];
    __syncthreads();

    float acc[NCLS];
    #pragma unroll
    for (int k = 0; k < NCLS; k++) acc[k] = 0.f;
    const float* xr = g_x + (b*MID + tid)*HW + n0;
    for (int n = 0; n < 512; n += 4) {
        float4 xv = *(const float4*)(xr + n);
        float vv[4] = {xv.x, xv.y, xv.z, xv.w};
        #pragma unroll
        for (int dn = 0; dn < 4; dn++) {
            float v = vv[dn];
            #pragma unroll
            for (int k = 0; k < NCLS; k++) acc[k] = fmaf(v, pw[k][n + dn], acc[k]);
        }
    }
    #pragma unroll
    for (int k = 0; k < NCLS; k++)
        atomicAdd(&g_ctx[(b*NCLS + k)*MID + tid], acc[k]);
}

// ---------------- k,v from normalized context ----------------
__global__ __launch_bounds__(256)
void kv_kernel(const float* __restrict__ k_w, const float* __restrict__ k_b,
               const float* __restrict__ v_w, const float* __restrict__ v_b) {
    int b  = blockIdx.x / NCLS;
    int kc = blockIdx.x % NCLS;
    __shared__ float ctx[MID];
    int tid = threadIdx.x;
    float S = fmaxf(g_S[b*NCLS + kc], 1e-6f);
    float invS = 1.f / S;
    for (int i = tid; i < MID; i += 256)
        ctx[i] = g_ctx[(b*NCLS + kc)*MID + i] * invS;
    __syncthreads();

    float kk = k_b[tid], vv = v_b[tid];
    const float4* kw4 = (const float4*)(k_w + tid*MID);
    const float4* vw4 = (const float4*)(v_w + tid*MID);
    for (int c4 = 0; c4 < MID/4; c4++) {
        float4 kw = kw4[c4], vw = vw4[c4];
        float c0 = ctx[c4*4], c1 = ctx[c4*4+1], c2 = ctx[c4*4+2], c3 = ctx[c4*4+3];
        kk = fmaf(c0, kw.x, fmaf(c1, kw.y, fmaf(c2, kw.z, fmaf(c3, kw.w, kk))));
        vv = fmaf(c0, vw.x, fmaf(c1, vw.y, fmaf(c2, vw.z, fmaf(c3, vw.w, vv))));
    }
    g_kmat[(b*NCLS + kc)*KCH + tid] = kk;
    g_vmat[(b*NCLS + kc)*VCH + tid] = vv;
}

// ---------------- gemm2 body (proven) ----------------
__device__ __forceinline__
void gemm2_body(const __half* __restrict__ Ahp, const __half* __restrict__ Alp,
                const __half* __restrict__ Bwp, int K, int Nst,
                float* __restrict__ outp, int mode, char* smc)
{
    uint32_t sbase = smem_u32(smc);
    int tid = threadIdx.x;
    int lane = tid & 31, warp = tid >> 5;
    int wm = warp & 3, wn = warp >> 2;
    int qrow = lane >> 2, qcol = (lane & 3) * 2;
    int n0 = blockIdx.x * 128;
    long pix0 = (long)blockIdx.y * 128;

    int arow = tid >> 1, ahalf = tid & 1;
    const __half* Abh = Ahp + (pix0 + arow) * K + ahalf * 16;
    const __half* Abl = Alp + (pix0 + arow) * K + ahalf * 16;
    const __half* Bb  = Bwp + (long)(n0 + arow) * K + ahalf * 16;
    uint32_t soff = (uint32_t)(arow * G2_STR + ahalf * 16) * 2;

    float d[2][8][4];
    #pragma unroll
    for (int mt = 0; mt < 2; mt++)
        #pragma unroll
        for (int nt = 0; nt < 8; nt++)
            #pragma unroll
            for (int e = 0; e < 4; e++) d[mt][nt][e] = 0.f;

    int nCh = K >> 5;
    {
        uint32_t st = sbase;
        cp16(st + soff,                Abh);  cp16(st + soff + 16,                Abh + 8);
        cp16(st + G2_REG*2 + soff,     Abl);  cp16(st + G2_REG*2 + soff + 16,     Abl + 8);
        cp16(st + 2*G2_REG*2 + soff,   Bb);   cp16(st + 2*G2_REG*2 + soff + 16,   Bb + 8);
        cp_commit();
    }
    for (int it = 0; it < nCh; it++) {
        int s = it & 1;
        if (it + 1 < nCh) {
            int c0 = (it + 1) * 32;
            uint32_t st = sbase + (uint32_t)(1 - s) * G2_STAGE;
            cp16(st + soff,              Abh + c0);  cp16(st + soff + 16,              Abh + c0 + 8);
            cp16(st + G2_REG*2 + soff,   Abl + c0);  cp16(st + G2_REG*2 + soff + 16,   Abl + c0 + 8);
            cp16(st + 2*G2_REG*2 + soff, Bb + c0);   cp16(st + 2*G2_REG*2 + soff + 16, Bb + c0 + 8);
            cp_commit();
            asm volatile("cp.async.wait_group 1;");
        } else {
            asm volatile("cp.async.wait_group 0;");
        }
        __syncthreads();

        const __half* sp = (const __half*)(smc + (size_t)s * G2_STAGE);
        const __half* Ah = sp;
        const __half* Al = sp + G2_REG;
        const __half* Bh = sp + 2*G2_REG;

        #pragma unroll
        for (int ks = 0; ks < 2; ks++) {
            int k0 = ks * 16 + qcol;
            uint32_t a[2][4], al[2][4], bh[8][2];
            #pragma unroll
            for (int mt = 0; mt < 2; mt++) {
                int r0 = wm * 32 + mt * 16 + qrow;
                a[mt][0] = *(const uint32_t*)(Ah + r0*G2_STR + k0);
                a[mt][1] = *(const uint32_t*)(Ah + (r0+8)*G2_STR + k0);
                a[mt][2] = *(const uint32_t*)(Ah + r0*G2_STR + k0 + 8);
                a[mt][3] = *(const uint32_t*)(Ah + (r0+8)*G2_STR + k0 + 8);
                al[mt][0] = *(const uint32_t*)(Al + r0*G2_STR + k0);
                al[mt][1] = *(const uint32_t*)(Al + (r0+8)*G2_STR + k0);
                al[mt][2] = *(const uint32_t*)(Al + r0*G2_STR + k0 + 8);
                al[mt][3] = *(const uint32_t*)(Al + (r0+8)*G2_STR + k0 + 8);
            }
            #pragma unroll
            for (int nt = 0; nt < 8; nt++) {
                int nn = wn * 64 + nt * 8 + qrow;
                bh[nt][0] = *(const uint32_t*)(Bh + nn*G2_STR + k0);
                bh[nt][1] = *(const uint32_t*)(Bh + nn*G2_STR + k0 + 8);
            }
            #pragma unroll
            for (int mt = 0; mt < 2; mt++)
                #pragma unroll
                for (int nt = 0; nt < 8; nt++) {
                    mma16816(d[mt][nt], a[mt], bh[nt]);
                    mma16816(d[mt][nt], al[mt], bh[nt]);
                }
        }
        __syncthreads();
    }

    if (mode == 0) {
        #pragma unroll
        for (int mt = 0; mt < 2; mt++) {
            long r = pix0 + wm * 32 + mt * 16 + qrow;
            #pragma unroll
            for (int nt = 0; nt < 8; nt++) {
                int ncol = n0 + wn * 64 + nt * 8 + qcol;
                float* p0 = outp + r * Nst + ncol;
                float* p1 = p0 + (long)8 * Nst;
                *(float2*)p0 = make_float2(d[mt][nt][0], d[mt][nt][1]);
                *(float2*)p1 = make_float2(d[mt][nt][2], d[mt][nt][3]);
            }
        }
    } else {
        float* es = (float*)smc;
        #pragma unroll
        for (int mt = 0; mt < 2; mt++) {
            int m = wm * 32 + mt * 16 + qrow;
            #pragma unroll
            for (int nt = 0; nt < 8; nt++) {
                int n = wn * 64 + nt * 8 + qcol;
                es[n*132 + m]       = d[mt][nt][0];
                es[(n+1)*132 + m]   = d[mt][nt][1];
                es[n*132 + m + 8]   = d[mt][nt][2];
                es[(n+1)*132 + m+8] = d[mt][nt][3];
            }
        }
        __syncthreads();
        int n = tid >> 1;
        int mh = (tid & 1) * 64;
        int b = (int)(pix0 >> 14);
        int hw0 = (int)(pix0 & (HW-1));
        float* dst = outp + ((long)(b * MID + n0 + n)) * HW + hw0 + mh;
        const float* src = es + n*132 + mh;
        #pragma unroll
        for (int j = 0; j < 16; j++) {
            float4 o = ((float4*)dst)[j];
            float4 a = ((const float4*)src)[j];
            o.x += a.x; o.y += a.y; o.z += a.z; o.w += a.w;
            ((float4*)dst)[j] = o;
        }
    }
}

__global__ void __launch_bounds__(256) gemm2_q() {
    extern __shared__ char smc[];
    gemm2_body(g_xh16, g_xl16, g_qw16, MID, KCH, g_q, 0, smc);
}
__global__ void __launch_bounds__(256) gemm2_obj() {
    extern __shared__ char smc[];
    gemm2_body(g_aggh, g_aggl, g_ow16, VCH, 0, g_x, 1, smc);
}

// ---------------- attention ----------------
__global__ __launch_bounds__(256)
void attention_kernel() {
    __shared__ float ks[NCLS*KCH];
    __shared__ float vs[NCLS*VCH];
    int tid = threadIdx.x;
    int pix = blockIdx.x * 256 + tid;
    int b = pix >> 14;
    for (int i = tid; i < NCLS*KCH; i += 256) ks[i] = g_kmat[b*NCLS*KCH + i];
    for (int i = tid; i < NCLS*VCH; i += 256) vs[i] = g_vmat[b*NCLS*VCH + i];
    __syncthreads();

    float s[NCLS];
    #pragma unroll
    for (int k = 0; k < NCLS; k++) s[k] = 0.f;
    const float4* qp = (const float4*)(g_q + (long)pix * KCH);
    for (int d4 = 0; d4 < KCH/4; d4++) {
        float4 q4 = qp[d4];
        float qv[4] = {q4.x, q4.y, q4.z, q4.w};
        #pragma unroll
        for (int j = 0; j < 4; j++) {
            float q = qv[j];
            int d = d4*4 + j;
            #pragma unroll
            for (int k = 0; k < NCLS; k++) s[k] = fmaf(q, ks[k*KCH + d], s[k]);
        }
    }
    const float scale = 0.0625f;
    float mx = -1e30f;
    #pragma unroll
    for (int k = 0; k < NCLS; k++) { s[k] *= scale; mx = fmaxf(mx, s[k]); }
    float sum = 0.f;
    #pragma unroll
    for (int k = 0; k < NCLS; k++) { s[k] = expf(s[k] - mx); sum += s[k]; }
    float inv = 1.f / sum;
    #pragma unroll
    for (int k = 0; k < NCLS; k++) s[k] *= inv;

    long pbase = (long)pix * VCH;
    for (int v0 = 0; v0 < VCH; v0 += 8) {
        __align__(16) __half hb[8];
        __align__(16) __half lb[8];
        #pragma unroll
        for (int vv = 0; vv < 8; vv++) {
            int v = v0 + vv;
            float o = 0.f;
            #pragma unroll
            for (int k = 0; k < NCLS; k++) o = fmaf(s[k], vs[k*VCH + v], o);
            __half h = __float2half_rn(o);
            hb[vv] = h;
            lb[vv] = __float2half_rn(o - __half2float(h));
        }
        *(uint4*)&g_aggh[pbase + v0] = *(const uint4*)hb;
        *(uint4*)&g_aggl[pbase + v0] = *(const uint4*)lb;
    }
}

// ---------------- cls head ----------------
__global__ __launch_bounds__(256)
void cls_kernel(const float* __restrict__ cls_w, const float* __restrict__ cls_b,
                float* __restrict__ logits) {
    __shared__ float sw[NCLS*MID];
    __shared__ float sb[NCLS];
    int tid = threadIdx.x;
    for (int i = tid; i < NCLS*MID; i += 256) sw[i] = cls_w[i];
    if (tid < NCLS) sb[tid] = cls_b[tid];
    __syncthreads();

    int pix = blockIdx.x * 256 + tid;
    int b = pix >> 14, hw = pix & (HW-1);
    float acc[NCLS];
    #pragma unroll
    for (int k = 0; k < NCLS; k++) acc[k] = 0.f;
    const float* xb = g_x + (long)b * MID * HW + hw;
    for (int c = 0; c < MID; c++) {
        float v = xb[(long)c*HW];
        #pragma unroll
        for (int k = 0; k < NCLS; k++) acc[k] = fmaf(v, sw[k*MID + c], acc[k]);
    }
    #pragma unroll
    for (int k = 0; k < NCLS; k++)
        logits[(b*NCLS + k)*HW + hw] = acc[k] + sb[k];
}

// ---------------- launch ----------------
extern "C" void kernel_launch(void* const* d_in, const int* in_sizes, int n_in,
                              void* d_out, int out_size) {
    const float* feats = (const float*)d_in[0];
    const float* w3    = (const float*)d_in[1];
    const float* gamma = (const float*)d_in[2];
    const float* beta  = (const float*)d_in[3];
    const float* aux_w = (const float*)d_in[4];
    const float* aux_b = (const float*)d_in[5];
    const float* q_w   = (const float*)d_in[6];
    const float* k_w   = (const float*)d_in[7];
    const float* k_b   = (const float*)d_in[8];
    const float* v_w   = (const float*)d_in[9];
    const float* v_b   = (const float*)d_in[10];
    const float* out_w = (const float*)d_in[11];
    const float* cls_w = (const float*)d_in[12];
    const float* cls_b = (const float*)d_in[13];

    float* logits  = (float*)d_out;
    float* aux_out = (float*)d_out + BSZ*NCLS*HW;

    cudaFuncSetAttribute(conv_mma, cudaFuncAttributeMaxDynamicSharedMemorySize, SMEM_DYN);
    cudaFuncSetAttribute(gemm2_q,   cudaFuncAttributeMaxDynamicSharedMemorySize, G2_SMEM);
    cudaFuncSetAttribute(gemm2_obj, cudaFuncAttributeMaxDynamicSharedMemorySize, G2_SMEM);

    long n4 = (long)BSZ*PH*PW*CIN / 8;
    zero_pad<<<(int)((n4 + 255) / 256), 256>>>();
    nhwc_prep<<<BSZ*IMG_H, 256>>>(feats);
    w3_prep<<<(9*MID*CIN + 255)/256, 256>>>(w3);
    w16_prep<<<(MID*VCH + 255)/256, 256>>>(q_w, out_w);
    zero_kernel<<<(BSZ*NCLS*MID + 255)/256, 256>>>();
    conv_mma<<<dim3(MID/128, BSZ*IMG_H), 128, SMEM_DYN>>>();
    bn_stats<<<MID, 256>>>(gamma, beta);
    bn_aux_softmax<<<BSZ*HW/256, 256>>>(aux_w, aux_b, aux_out);
    context_kernel<<<dim3(HW/512, BSZ), 512>>>();
    kv_kernel<<<BSZ*NCLS, 256>>>(k_w, k_b, v_w, v_b);
    gemm2_q<<<dim3(KCH/128, BSZ*HW/128), 256, G2_SMEM>>>();
    attention_kernel<<<BSZ*HW/256, 256>>>();
    gemm2_obj<<<dim3(MID/128, BSZ*HW/128), 256, G2_SMEM>>>();
    cls_kernel<<<BSZ*HW/256, 256>>>(cls_w, cls_b, logits);
}

// round 15
// speedup vs baseline: 1.0871x; 1.0871x over previous
#include <cuda_runtime.h>
#include <cuda_fp16.h>
#include <math.h>
#include <cstdint>

#define HW     16384
#define IMG_H  128
#define IMG_W  128
#define BSZ    4
#define CIN    720
#define MID    512
#define NCLS   19
#define KCH    256
#define VCH    256

#define PH 130
#define PW 130

// conv tiling (R13, proven best): CTA 128(m) x 256(n), K-chunk 48, 8 warps (2m x 4n), warp 64x64
#define KCH_C     48
#define NCHUNKS   135
#define ASTRIDE   56
#define REG_A_ELE (128*ASTRIDE)          // 7168
#define REG_B_ELE (256*ASTRIDE)          // 14336
#define STG_ELE   (REG_A_ELE + REG_B_ELE)
#define STG_BYTES (STG_ELE*2)            // 43008
#define SMEM_DYN  (2*STG_BYTES)          // 86016

// gemm2 tiling (proven)
#define G2_STR    40
#define G2_REG    (128*G2_STR)
#define G2_STAGE  (3*G2_REG*2)           // 30720
#define G2_SMEM   67584

// ---------------- scratch ----------------
__device__ float g_x    [BSZ*MID*HW];
__device__ float g_q    [BSZ*HW*KCH];
__device__ float g_probs[BSZ*NCLS*HW];
__device__ float g_S    [BSZ*NCLS];
__device__ float g_ctx  [BSZ*NCLS*MID];
__device__ float g_kmat [BSZ*NCLS*KCH];
__device__ float g_vmat [BSZ*NCLS*VCH];
__device__ float g_scale[MID];
__device__ float g_shift[MID];
__device__ float g_sum  [MID];
__device__ float g_sumsq[MID];
__device__ __align__(16) __half g_fhi[BSZ*PH*PW*CIN];
__device__ __align__(16) __half g_whi[9*MID*CIN];
__device__ __align__(16) __half g_xh16[BSZ*HW*MID];
__device__ __align__(16) __half g_xl16[BSZ*HW*MID];
__device__ __align__(16) __half g_aggh[BSZ*HW*VCH];
__device__ __align__(16) __half g_aggl[BSZ*HW*VCH];
__device__ __align__(16) __half g_qw16[KCH*MID];
__device__ __align__(16) __half g_ow16[MID*VCH];

// ---------------- helpers ----------------
__device__ __forceinline__ uint32_t smem_u32(const void* p) {
    uint32_t a;
    asm("{ .reg .u64 t; cvta.to.shared.u64 t, %1; cvt.u32.u64 %0, t; }" : "=r"(a) : "l"(p));
    return a;
}
__device__ __forceinline__ void cp16(uint32_t s, const void* g) {
    asm volatile("cp.async.cg.shared.global [%0], [%1], 16;" :: "r"(s), "l"(g));
}
__device__ __forceinline__ void cp_commit() {
    asm volatile("cp.async.commit_group;");
}
__device__ __forceinline__ void mma16816(float* d, const uint32_t* a, const uint32_t* b) {
    asm volatile(
        "mma.sync.aligned.m16n8k16.row.col.f32.f16.f16.f32 "
        "{%0,%1,%2,%3}, {%4,%5,%6,%7}, {%8,%9}, {%0,%1,%2,%3};"
        : "+f"(d[0]), "+f"(d[1]), "+f"(d[2]), "+f"(d[3])
        : "r"(a[0]), "r"(a[1]), "r"(a[2]), "r"(a[3]), "r"(b[0]), "r"(b[1]));
}

// ---------------- merged prep: zero buffers + all weight conversions ----------------
__global__ void prep_all(const float* __restrict__ w3,
                         const float* __restrict__ qw,
                         const float* __restrict__ ow) {
    long i = (long)blockIdx.x * 256 + threadIdx.x;
    const long n4 = (long)BSZ*PH*PW*CIN / 8;
    if (i < n4) ((float4*)g_fhi)[i] = make_float4(0.f, 0.f, 0.f, 0.f);
    if (i < 9*MID*CIN) {
        int r = (int)(i / (MID * CIN));
        int rem = (int)(i - (long)r * (MID * CIN));
        int o = rem / CIN;
        int c = rem - o * CIN;
        g_whi[i] = __float2half_rn(w3[(o * CIN + c) * 9 + r]);
    }
    if (i < KCH*MID) g_qw16[i] = __float2half_rn(qw[i]);
    if (i < MID*VCH) g_ow16[i] = __float2half_rn(ow[i]);
    if (i < BSZ*NCLS*MID) g_ctx[i] = 0.f;
    if (i < BSZ*NCLS)     g_S[i]   = 0.f;
    if (i < MID) { g_sum[i] = 0.f; g_sumsq[i] = 0.f; }
}

// ---------------- prep: NHWC fp16 of feats (padded) ----------------
__global__ __launch_bounds__(256) void nhwc_prep(const float* __restrict__ feats) {
    __shared__ float tile[64][129];
    int by = blockIdx.x;
    int b = by >> 7, h = by & 127;
    int tid = threadIdx.x;
    const float* fb = feats + ((long)b * CIN) * HW + h * IMG_W;
    long obase = ((long)(b * PH + h + 1) * PW + 1) * CIN;
    for (int c0 = 0; c0 < CIN; c0 += 64) {
        int cw = CIN - c0; if (cw > 64) cw = 64;
        #pragma unroll 4
        for (int j = 0; j < 32; j++) {
            int idx = tid + j * 256;
            int c = idx >> 7, w = idx & 127;
            if (c < cw) tile[c][w] = fb[(long)(c0 + c) * HW + w];
        }
        __syncthreads();
        #pragma unroll 4
        for (int j = 0; j < 32; j++) {
            int idx = tid + j * 256;
            int w = idx >> 6, c = idx & 63;
            if (c < cw)
                g_fhi[obase + (long)w * CIN + c0 + c] = __float2half_rn(tile[c][w]);
        }
        __syncthreads();
    }
}

// ---------------- conv3x3 (R13) + fused BN-stat partials in epilogue ----------------
__global__ __launch_bounds__(256) void conv_mma() {
    extern __shared__ __half sm[];
    uint32_t sbase = smem_u32(sm);
    int tid = threadIdx.x;
    int lane = tid & 31, warp = tid >> 5;
    int wm = warp & 1, wn = warp >> 1;           // 2m x 4n
    int qrow = lane >> 2, qcol = (lane & 3) * 2;
    int bn = blockIdx.x * 256;
    int by = blockIdx.y;
    int b = by >> 7, h = by & 127;

    const __half* fhi_b = g_fhi + (long)b * PH * PW * CIN;

    int lrow = tid >> 1, lhalf = tid & 1;
    int thr_g = lrow * CIN + lhalf * 24;
    uint32_t thr_s = (uint32_t)(lrow * ASTRIDE + lhalf * 24) * 2;

    float d[4][8][4];
    #pragma unroll
    for (int mt = 0; mt < 4; mt++)
        #pragma unroll
        for (int nt = 0; nt < 8; nt++)
            #pragma unroll
            for (int e = 0; e < 4; e++) d[mt][nt][e] = 0.f;

    int nr = 0, nci = 0, nc0 = 0;

    {
        int ab = h * PW * CIN + thr_g;
        uint32_t st = sbase;
        #pragma unroll
        for (int j = 0; j < 3; j++)
            cp16(st + thr_s + j*16, fhi_b + ab + j*8);
        #pragma unroll
        for (int g = 0; g < 2; g++) {
            int bb = (bn + g*128) * CIN + thr_g;
            uint32_t bs = REG_A_ELE*2 + (uint32_t)(g*128*ASTRIDE)*2 + thr_s;
            #pragma unroll
            for (int j = 0; j < 3; j++)
                cp16(st + bs + j*16, g_whi + bb + j*8);
        }
        cp_commit();
    }
    nci = 1; nc0 = KCH_C;

    for (int it = 0; it < NCHUNKS; it++) {
        int s = it & 1;
        if (it + 1 < NCHUNKS) {
            int ky = nr / 3, kx = nr - ky * 3;
            int ab = ((h + ky) * PW + kx) * CIN + nc0 + thr_g;
            uint32_t st = sbase + (uint32_t)(1 - s) * STG_BYTES;
            #pragma unroll
            for (int j = 0; j < 3; j++)
                cp16(st + thr_s + j*16, fhi_b + ab + j*8);
            #pragma unroll
            for (int g = 0; g < 2; g++) {
                int bb = (nr * MID + bn + g*128) * CIN + nc0 + thr_g;
                uint32_t bs = REG_A_ELE*2 + (uint32_t)(g*128*ASTRIDE)*2 + thr_s;
                #pragma unroll
                for (int j = 0; j < 3; j++)
                    cp16(st + bs + j*16, g_whi + bb + j*8);
            }
            cp_commit();
            nci++; nc0 += KCH_C;
            if (nci == 15) { nci = 0; nc0 = 0; nr++; }
            asm volatile("cp.async.wait_group 1;");
        } else {
            asm volatile("cp.async.wait_group 0;");
        }
        __syncthreads();

        const __half* st = sm + (size_t)s * STG_ELE;
        const __half* Ah = st;
        const __half* Bh = st + REG_A_ELE;

        #pragma unroll
        for (int ks = 0; ks < 3; ks++) {
            int k0 = ks * 16 + qcol;
            uint32_t ah[4][4], bh[8][2];
            #pragma unroll
            for (int mt = 0; mt < 4; mt++) {
                int r0 = wm * 64 + mt * 16 + qrow;
                ah[mt][0] = *(const uint32_t*)(Ah + r0*ASTRIDE + k0);
                ah[mt][1] = *(const uint32_t*)(Ah + (r0+8)*ASTRIDE + k0);
                ah[mt][2] = *(const uint32_t*)(Ah + r0*ASTRIDE + k0 + 8);
                ah[mt][3] = *(const uint32_t*)(Ah + (r0+8)*ASTRIDE + k0 + 8);
            }
            #pragma unroll
            for (int nt = 0; nt < 8; nt++) {
                int n0r = wn * 64 + nt * 8 + qrow;
                bh[nt][0] = *(const uint32_t*)(Bh + n0r*ASTRIDE + k0);
                bh[nt][1] = *(const uint32_t*)(Bh + n0r*ASTRIDE + k0 + 8);
            }
            #pragma unroll
            for (int mt = 0; mt < 4; mt++)
                #pragma unroll
                for (int nt = 0; nt < 8; nt++)
                    mma16816(d[mt][nt], ah[mt], bh[nt]);
        }
        __syncthreads();
    }

    // epilogue: two 128-channel halves through SMEM transpose; fused BN-stat partials
    float* es = (float*)sm;   // [128 n][132 m]
    #pragma unroll
    for (int nh = 0; nh < 2; nh++) {
        if ((wn >> 1) == nh) {
            #pragma unroll
            for (int mt = 0; mt < 4; mt++) {
                int m = wm * 64 + mt * 16 + qrow;
                #pragma unroll
                for (int nt = 0; nt < 8; nt++) {
                    int n = (wn & 1) * 64 + nt * 8 + qcol;
                    es[n*132 + m]       = d[mt][nt][0];
                    es[(n+1)*132 + m]   = d[mt][nt][1];
                    es[n*132 + m + 8]   = d[mt][nt][2];
                    es[(n+1)*132 + m+8] = d[mt][nt][3];
                }
            }
        }
        __syncthreads();
        {
            int n = tid >> 1;
            int mh = (tid & 1) * 64;
            float* dst = g_x + ((long)(b * MID + bn + nh*128 + n)) * HW + h * IMG_W + mh;
            const float* src = es + n*132 + mh;
            float s = 0.f, sq = 0.f;
            #pragma unroll
            for (int j = 0; j < 16; j++) {
                float4 v = ((const float4*)src)[j];
                ((float4*)dst)[j] = v;
                s  += v.x + v.y + v.z + v.w;
                sq += v.x*v.x + v.y*v.y + v.z*v.z + v.w*v.w;
            }
            s  += __shfl_down_sync(0xffffffffu, s, 1);
            sq += __shfl_down_sync(0xffffffffu, sq, 1);
            if ((tid & 1) == 0) {
                atomicAdd(&g_sum[bn + nh*128 + n], s);
                atomicAdd(&g_sumsq[bn + nh*128 + n], sq);
            }
        }
        __syncthreads();
    }
}

// ---------------- BN finalize (tiny) ----------------
__global__ void bn_finalize(const float* __restrict__ gamma, const float* __restrict__ beta) {
    int c = blockIdx.x * 256 + threadIdx.x;
    if (c >= MID) return;
    float n    = (float)(BSZ*HW);
    float mean = g_sum[c] / n;
    float var  = g_sumsq[c] / n - mean*mean;
    float rstd = rsqrtf(var + 1e-5f);
    float sc   = gamma[c] * rstd;
    g_scale[c] = sc;
    g_shift[c] = beta[c] - mean * sc;
}

// ---------------- fused: BN apply + relu + fp16 split emit [pix][c] + aux + softmax ----------------
__global__ __launch_bounds__(256)
void bn_aux_softmax(const float* __restrict__ aux_w, const float* __restrict__ aux_b,
                    float* __restrict__ aux_out) {
    __shared__ float sw[NCLS*MID];
    __shared__ float ssc[MID], ssh[MID];
    __shared__ float sb[NCLS], sS[NCLS];
    int tid = threadIdx.x;
    for (int i = tid; i < NCLS*MID; i += 256) sw[i] = aux_w[i];
    for (int i = tid; i < MID; i += 256) { ssc[i] = g_scale[i]; ssh[i] = g_shift[i]; }
    if (tid < NCLS) { sb[tid] = aux_b[tid]; sS[tid] = 0.f; }
    __syncthreads();

    int pix = blockIdx.x * 256 + tid;
    int b   = pix >> 14;
    int hw  = pix & (HW-1);
    float acc[NCLS];
    #pragma unroll
    for (int k = 0; k < NCLS; k++) acc[k] = 0.f;

    float* xb = g_x + (long)b * MID * HW + hw;
    long pbase = (long)pix * MID;
    for (int c0 = 0; c0 < MID; c0 += 8) {
        __align__(16) __half hb[8];
        __align__(16) __half lb[8];
        #pragma unroll
        for (int cc = 0; cc < 8; cc++) {
            int c = c0 + cc;
            float v = xb[(long)c*HW];
            v = fmaf(v, ssc[c], ssh[c]);
            v = fmaxf(v, 0.f);
            xb[(long)c*HW] = v;
            __half hv = __float2half_rn(v);
            hb[cc] = hv;
            lb[cc] = __float2half_rn(v - __half2float(hv));
            #pragma unroll
            for (int k = 0; k < NCLS; k++) acc[k] = fmaf(v, sw[k*MID + c], acc[k]);
        }
        *(uint4*)&g_xh16[pbase + c0] = *(const uint4*)hb;
        *(uint4*)&g_xl16[pbase + c0] = *(const uint4*)lb;
    }
    float mx = -1e30f;
    #pragma unroll
    for (int k = 0; k < NCLS; k++) {
        acc[k] += sb[k];
        aux_out[(b*NCLS + k)*HW + hw] = acc[k];
        mx = fmaxf(mx, acc[k]);
    }
    float sum = 0.f;
    #pragma unroll
    for (int k = 0; k < NCLS; k++) { acc[k] = expf(acc[k] - mx); sum += acc[k]; }
    float inv = 1.f / sum;
    #pragma unroll
    for (int k = 0; k < NCLS; k++) {
        float p = acc[k] * inv;
        g_probs[(b*NCLS + k)*HW + hw] = p;
        atomicAdd(&sS[k], p);
    }
    __syncthreads();
    if (tid < NCLS) atomicAdd(&g_S[b*NCLS + tid], sS[tid]);
}

// ---------------- context ----------------
__global__ __launch_bounds__(512)
void context_kernel() {
    __shared__ float pw[NCLS][512];
    int b   = blockIdx.y;
    int n0  = blockIdx.x * 512;
    int tid = threadIdx.x;
    for (int k = 0; k < NCLS; k++)
        pw[k][tid] = g_probs[(b*NCLS + k)*HW + n0 + tid];
    __syncthreads();

    float acc[NCLS];
    #pragma unroll
    for (int k = 0; k < NCLS; k++) acc[k] = 0.f;
    const float* xr = g_x + (b*MID + tid)*HW + n0;
    for (int n = 0; n < 512; n += 4) {
        float4 xv = *(const float4*)(xr + n);
        float vv[4] = {xv.x, xv.y, xv.z, xv.w};
        #pragma unroll
        for (int dn = 0; dn < 4; dn++) {
            float v = vv[dn];
            #pragma unroll
            for (int k = 0; k < NCLS; k++) acc[k] = fmaf(v, pw[k][n + dn], acc[k]);
        }
    }
    #pragma unroll
    for (int k = 0; k < NCLS; k++)
        atomicAdd(&g_ctx[(b*NCLS + k)*MID + tid], acc[k]);
}

// ---------------- k,v from normalized context ----------------
__global__ __launch_bounds__(256)
void kv_kernel(const float* __restrict__ k_w, const float* __restrict__ k_b,
               const float* __restrict__ v_w, const float* __restrict__ v_b) {
    int b  = blockIdx.x / NCLS;
    int kc = blockIdx.x % NCLS;
    __shared__ float ctx[MID];
    int tid = threadIdx.x;
    float S = fmaxf(g_S[b*NCLS + kc], 1e-6f);
    float invS = 1.f / S;
    for (int i = tid; i < MID; i += 256)
        ctx[i] = g_ctx[(b*NCLS + kc)*MID + i] * invS;
    __syncthreads();

    float kk = k_b[tid], vv = v_b[tid];
    const float4* kw4 = (const float4*)(k_w + tid*MID);
    const float4* vw4 = (const float4*)(v_w + tid*MID);
    for (int c4 = 0; c4 < MID/4; c4++) {
        float4 kw = kw4[c4], vw = vw4[c4];
        float c0 = ctx[c4*4], c1 = ctx[c4*4+1], c2 = ctx[c4*4+2], c3 = ctx[c4*4+3];
        kk = fmaf(c0, kw.x, fmaf(c1, kw.y, fmaf(c2, kw.z, fmaf(c3, kw.w, kk))));
        vv = fmaf(c0, vw.x, fmaf(c1, vw.y, fmaf(c2, vw.z, fmaf(c3, vw.w, vv))));
    }
    g_kmat[(b*NCLS + kc)*KCH + tid] = kk;
    g_vmat[(b*NCLS + kc)*VCH + tid] = vv;
}

// ---------------- gemm2 body (proven) ----------------
__device__ __forceinline__
void gemm2_body(const __half* __restrict__ Ahp, const __half* __restrict__ Alp,
                const __half* __restrict__ Bwp, int K, int Nst,
                float* __restrict__ outp, int mode, char* smc)
{
    uint32_t sbase = smem_u32(smc);
    int tid = threadIdx.x;
    int lane = tid & 31, warp = tid >> 5;
    int wm = warp & 3, wn = warp >> 2;
    int qrow = lane >> 2, qcol = (lane & 3) * 2;
    int n0 = blockIdx.x * 128;
    long pix0 = (long)blockIdx.y * 128;

    int arow = tid >> 1, ahalf = tid & 1;
    const __half* Abh = Ahp + (pix0 + arow) * K + ahalf * 16;
    const __half* Abl = Alp + (pix0 + arow) * K + ahalf * 16;
    const __half* Bb  = Bwp + (long)(n0 + arow) * K + ahalf * 16;
    uint32_t soff = (uint32_t)(arow * G2_STR + ahalf * 16) * 2;

    float d[2][8][4];
    #pragma unroll
    for (int mt = 0; mt < 2; mt++)
        #pragma unroll
        for (int nt = 0; nt < 8; nt++)
            #pragma unroll
            for (int e = 0; e < 4; e++) d[mt][nt][e] = 0.f;

    int nCh = K >> 5;
    {
        uint32_t st = sbase;
        cp16(st + soff,                Abh);  cp16(st + soff + 16,                Abh + 8);
        cp16(st + G2_REG*2 + soff,     Abl);  cp16(st + G2_REG*2 + soff + 16,     Abl + 8);
        cp16(st + 2*G2_REG*2 + soff,   Bb);   cp16(st + 2*G2_REG*2 + soff + 16,   Bb + 8);
        cp_commit();
    }
    for (int it = 0; it < nCh; it++) {
        int s = it & 1;
        if (it + 1 < nCh) {
            int c0 = (it + 1) * 32;
            uint32_t st = sbase + (uint32_t)(1 - s) * G2_STAGE;
            cp16(st + soff,              Abh + c0);  cp16(st + soff + 16,              Abh + c0 + 8);
            cp16(st + G2_REG*2 + soff,   Abl + c0);  cp16(st + G2_REG*2 + soff + 16,   Abl + c0 + 8);
            cp16(st + 2*G2_REG*2 + soff, Bb + c0);   cp16(st + 2*G2_REG*2 + soff + 16, Bb + c0 + 8);
            cp_commit();
            asm volatile("cp.async.wait_group 1;");
        } else {
            asm volatile("cp.async.wait_group 0;");
        }
        __syncthreads();

        const __half* sp = (const __half*)(smc + (size_t)s * G2_STAGE);
        const __half* Ah = sp;
        const __half* Al = sp + G2_REG;
        const __half* Bh = sp + 2*G2_REG;

        #pragma unroll
        for (int ks = 0; ks < 2; ks++) {
            int k0 = ks * 16 + qcol;
            uint32_t a[2][4], al[2][4], bh[8][2];
            #pragma unroll
            for (int mt = 0; mt < 2; mt++) {
                int r0 = wm * 32 + mt * 16 + qrow;
                a[mt][0] = *(const uint32_t*)(Ah + r0*G2_STR + k0);
                a[mt][1] = *(const uint32_t*)(Ah + (r0+8)*G2_STR + k0);
                a[mt][2] = *(const uint32_t*)(Ah + r0*G2_STR + k0 + 8);
                a[mt][3] = *(const uint32_t*)(Ah + (r0+8)*G2_STR + k0 + 8);
                al[mt][0] = *(const uint32_t*)(Al + r0*G2_STR + k0);
                al[mt][1] = *(const uint32_t*)(Al + (r0+8)*G2_STR + k0);
                al[mt][2] = *(const uint32_t*)(Al + r0*G2_STR + k0 + 8);
                al[mt][3] = *(const uint32_t*)(Al + (r0+8)*G2_STR + k0 + 8);
            }
            #pragma unroll
            for (int nt = 0; nt < 8; nt++) {
                int nn = wn * 64 + nt * 8 + qrow;
                bh[nt][0] = *(const uint32_t*)(Bh + nn*G2_STR + k0);
                bh[nt][1] = *(const uint32_t*)(Bh + nn*G2_STR + k0 + 8);
            }
            #pragma unroll
            for (int mt = 0; mt < 2; mt++)
                #pragma unroll
                for (int nt = 0; nt < 8; nt++) {
                    mma16816(d[mt][nt], a[mt], bh[nt]);
                    mma16816(d[mt][nt], al[mt], bh[nt]);
                }
        }
        __syncthreads();
    }

    if (mode == 0) {
        #pragma unroll
        for (int mt = 0; mt < 2; mt++) {
            long r = pix0 + wm * 32 + mt * 16 + qrow;
            #pragma unroll
            for (int nt = 0; nt < 8; nt++) {
                int ncol = n0 + wn * 64 + nt * 8 + qcol;
                float* p0 = outp + r * Nst + ncol;
                float* p1 = p0 + (long)8 * Nst;
                *(float2*)p0 = make_float2(d[mt][nt][0], d[mt][nt][1]);
                *(float2*)p1 = make_float2(d[mt][nt][2], d[mt][nt][3]);
            }
        }
    } else {
        float* es = (float*)smc;
        #pragma unroll
        for (int mt = 0; mt < 2; mt++) {
            int m = wm * 32 + mt * 16 + qrow;
            #pragma unroll
            for (int nt = 0; nt < 8; nt++) {
                int n = wn * 64 + nt * 8 + qcol;
                es[n*132 + m]       = d[mt][nt][0];
                es[(n+1)*132 + m]   = d[mt][nt][1];
                es[n*132 + m + 8]   = d[mt][nt][2];
                es[(n+1)*132 + m+8] = d[mt][nt][3];
            }
        }
        __syncthreads();
        int n = tid >> 1;
        int mh = (tid & 1) * 64;
        int b = (int)(pix0 >> 14);
        int hw0 = (int)(pix0 & (HW-1));
        float* dst = outp + ((long)(b * MID + n0 + n)) * HW + hw0 + mh;
        const float* src = es + n*132 + mh;
        #pragma unroll
        for (int j = 0; j < 16; j++) {
            float4 o = ((float4*)dst)[j];
            float4 a = ((const float4*)src)[j];
            o.x += a.x; o.y += a.y; o.z += a.z; o.w += a.w;
            ((float4*)dst)[j] = o;
        }
    }
}

__global__ void __launch_bounds__(256) gemm2_q() {
    extern __shared__ char smc[];
    gemm2_body(g_xh16, g_xl16, g_qw16, MID, KCH, g_q, 0, smc);
}
__global__ void __launch_bounds__(256) gemm2_obj() {
    extern __shared__ char smc[];
    gemm2_body(g_aggh, g_aggl, g_ow16, VCH, 0, g_x, 1, smc);
}

// ---------------- attention ----------------
__global__ __launch_bounds__(256)
void attention_kernel() {
    __shared__ float ks[NCLS*KCH];
    __shared__ float vs[NCLS*VCH];
    int tid = threadIdx.x;
    int pix = blockIdx.x * 256 + tid;
    int b = pix >> 14;
    for (int i = tid; i < NCLS*KCH; i += 256) ks[i] = g_kmat[b*NCLS*KCH + i];
    for (int i = tid; i < NCLS*VCH; i += 256) vs[i] = g_vmat[b*NCLS*VCH + i];
    __syncthreads();

    float s[NCLS];
    #pragma unroll
    for (int k = 0; k < NCLS; k++) s[k] = 0.f;
    const float4* qp = (const float4*)(g_q + (long)pix * KCH);
    for (int d4 = 0; d4 < KCH/4; d4++) {
        float4 q4 = qp[d4];
        float qv[4] = {q4.x, q4.y, q4.z, q4.w};
        #pragma unroll
        for (int j = 0; j < 4; j++) {
            float q = qv[j];
            int d = d4*4 + j;
            #pragma unroll
            for (int k = 0; k < NCLS; k++) s[k] = fmaf(q, ks[k*KCH + d], s[k]);
        }
    }
    const float scale = 0.0625f;
    float mx = -1e30f;
    #pragma unroll
    for (int k = 0; k < NCLS; k++) { s[k] *= scale; mx = fmaxf(mx, s[k]); }
    float sum = 0.f;
    #pragma unroll
    for (int k = 0; k < NCLS; k++) { s[k] = expf(s[k] - mx); sum += s[k]; }
    float inv = 1.f / sum;
    #pragma unroll
    for (int k = 0; k < NCLS; k++) s[k] *= inv;

    long pbase = (long)pix * VCH;
    for (int v0 = 0; v0 < VCH; v0 += 8) {
        __align__(16) __half hb[8];
        __align__(16) __half lb[8];
        #pragma unroll
        for (int vv = 0; vv < 8; vv++) {
            int v = v0 + vv;
            float o = 0.f;
            #pragma unroll
            for (int k = 0; k < NCLS; k++) o = fmaf(s[k], vs[k*VCH + v], o);
            __half h = __float2half_rn(o);
            hb[vv] = h;
            lb[vv] = __float2half_rn(o - __half2float(h));
        }
        *(uint4*)&g_aggh[pbase + v0] = *(const uint4*)hb;
        *(uint4*)&g_aggl[pbase + v0] = *(const uint4*)lb;
    }
}

// ---------------- cls head ----------------
__global__ __launch_bounds__(256)
void cls_kernel(const float* __restrict__ cls_w, const float* __restrict__ cls_b,
                float* __restrict__ logits) {
    __shared__ float sw[NCLS*MID];
    __shared__ float sb[NCLS];
    int tid = threadIdx.x;
    for (int i = tid; i < NCLS*MID; i += 256) sw[i] = cls_w[i];
    if (tid < NCLS) sb[tid] = cls_b[tid];
    __syncthreads();

    int pix = blockIdx.x * 256 + tid;
    int b = pix >> 14, hw = pix & (HW-1);
    float acc[NCLS];
    #pragma unroll
    for (int k = 0; k < NCLS; k++) acc[k] = 0.f;
    const float* xb = g_x + (long)b * MID * HW + hw;
    for (int c = 0; c < MID; c++) {
        float v = xb[(long)c*HW];
        #pragma unroll
        for (int k = 0; k < NCLS; k++) acc[k] = fmaf(v, sw[k*MID + c], acc[k]);
    }
    #pragma unroll
    for (int k = 0; k < NCLS; k++)
        logits[(b*NCLS + k)*HW + hw] = acc[k] + sb[k];
}

// ---------------- launch ----------------
extern "C" void kernel_launch(void* const* d_in, const int* in_sizes, int n_in,
                              void* d_out, int out_size) {
    const float* feats = (const float*)d_in[0];
    const float* w3    = (const float*)d_in[1];
    const float* gamma = (const float*)d_in[2];
    const float* beta  = (const float*)d_in[3];
    const float* aux_w = (const float*)d_in[4];
    const float* aux_b = (const float*)d_in[5];
    const float* q_w   = (const float*)d_in[6];
    const float* k_w   = (const float*)d_in[7];
    const float* k_b   = (const float*)d_in[8];
    const float* v_w   = (const float*)d_in[9];
    const float* v_b   = (const float*)d_in[10];
    const float* out_w = (const float*)d_in[11];
    const float* cls_w = (const float*)d_in[12];
    const float* cls_b = (const float*)d_in[13];

    float* logits  = (float*)d_out;
    float* aux_out = (float*)d_out + BSZ*NCLS*HW;

    cudaFuncSetAttribute(conv_mma, cudaFuncAttributeMaxDynamicSharedMemorySize, SMEM_DYN);
    cudaFuncSetAttribute(gemm2_q,   cudaFuncAttributeMaxDynamicSharedMemorySize, G2_SMEM);
    cudaFuncSetAttribute(gemm2_obj, cudaFuncAttributeMaxDynamicSharedMemorySize, G2_SMEM);

    long n4 = (long)BSZ*PH*PW*CIN / 8;   // largest range in prep_all
    prep_all<<<(int)((n4 + 255) / 256), 256>>>(w3, q_w, out_w);
    nhwc_prep<<<BSZ*IMG_H, 256>>>(feats);
    conv_mma<<<dim3(MID/256, BSZ*IMG_H), 256, SMEM_DYN>>>();
    bn_finalize<<<2, 256>>>(gamma, beta);
    bn_aux_softmax<<<BSZ*HW/256, 256>>>(aux_w, aux_b, aux_out);
    context_kernel<<<dim3(HW/512, BSZ), 512>>>();
    kv_kernel<<<BSZ*NCLS, 256>>>(k_w, k_b, v_w, v_b);
    gemm2_q<<<dim3(KCH/128, BSZ*HW/128), 256, G2_SMEM>>>();
    attention_kernel<<<BSZ*HW/256, 256>>>();
    gemm2_obj<<<dim3(MID/128, BSZ*HW/128), 256, G2_SMEM>>>();
    cls_kernel<<<BSZ*HW/256, 256>>>(cls_w, cls_b, logits);
}